// round 17
// baseline (speedup 1.0000x reference)
#include <cuda_runtime.h>
#include <cuda_fp16.h>
#include <math.h>
#include <stdint.h>

#define TT   4096
#define DM   1024
#define HH   4096
#define NE   8
#define NSEG 9
#define CAP  4096

// smem: per stage A(128x144B) + B(128x144B); 3 stages; 2 CTAs/SM
#define A_TILE_B 18432
#define B_TILE_B 18432
#define STAGE_B  36864
#define SMEM_SZ  110592

// fused aux kernel block ranges
#define WCVT_BLKS  73728
#define ZERO_BLKS  4096
#define GATE_BLKS  512

// merged gemm grid
#define G1_TILES   9216          // 32(n) x 32(m) x 9(seg)
#define G2_TILES   2304          // 8(n) x 32(m) x 9(seg)

// ---------------- scratch (__device__ globals; allocation-free rule) -------
__device__ int   g_cnt[NSEG];
__device__ int   g_rowmap[NE * CAP];
__device__ float g_sgate[NE * CAP];
__device__ int   g_ticket;
__device__ int   g_done[NSEG * 32];

__device__ __align__(16) __half g_x [(size_t)NSEG * CAP * DM];
__device__ __align__(16) __half g_w1[(size_t)NSEG * HH * DM];
__device__ __align__(16) __half g_w2[(size_t)NSEG * DM * HH];
__device__ __align__(16) __half g_h [(size_t)NSEG * CAP * HH];

// ---------------- helpers ---------------------------------------------------
__device__ __forceinline__ uint32_t s2u(const void* p) {
    uint32_t a;
    asm("{ .reg .u64 t; cvta.to.shared.u64 t, %1; cvt.u32.u64 %0, t; }" : "=r"(a) : "l"(p));
    return a;
}
__device__ __forceinline__ void cpasync16(uint32_t dst, const void* src) {
    asm volatile("cp.async.cg.shared.global [%0], [%1], 16;" :: "r"(dst), "l"(src) : "memory");
}
__device__ __forceinline__ void cp_commit() { asm volatile("cp.async.commit_group;" ::: "memory"); }
template <int N> __device__ __forceinline__ void cp_wait() {
    asm volatile("cp.async.wait_group %0;" :: "n"(N) : "memory");
}
__device__ __forceinline__ void ldsm4(uint32_t* r, uint32_t a) {
    asm volatile("ldmatrix.sync.aligned.m8n8.x4.shared.b16 {%0,%1,%2,%3}, [%4];"
                 : "=r"(r[0]), "=r"(r[1]), "=r"(r[2]), "=r"(r[3]) : "r"(a));
}
__device__ __forceinline__ void ldsm2(uint32_t* r, uint32_t a) {
    asm volatile("ldmatrix.sync.aligned.m8n8.x2.shared.b16 {%0,%1}, [%2];"
                 : "=r"(r[0]), "=r"(r[1]) : "r"(a));
}
__device__ __forceinline__ void mma16816(float* c, const uint32_t* a, const uint32_t* b) {
    asm volatile("mma.sync.aligned.m16n8k16.row.col.f32.f16.f16.f32 "
                 "{%0,%1,%2,%3}, {%4,%5,%6,%7}, {%8,%9}, {%0,%1,%2,%3};"
                 : "+f"(c[0]), "+f"(c[1]), "+f"(c[2]), "+f"(c[3])
                 : "r"(a[0]), "r"(a[1]), "r"(a[2]), "r"(a[3]), "r"(b[0]), "r"(b[1]));
}
// silu via hardware tanh: x * (0.5 + 0.5*tanh(x/2)) — 1 MUFU instead of 2
__device__ __forceinline__ float silu_f(float v) {
    float t;
    asm("tanh.approx.f32 %0, %1;" : "=f"(t) : "f"(0.5f * v));
    return v * fmaf(0.5f, t, 0.5f);
}
// vectorized global reduction: one REDG for 4 floats (PTX 8.1+, sm_90+)
__device__ __forceinline__ void red_add_v4(float* addr, float a, float b, float c, float d) {
    asm volatile("red.global.add.v4.f32 [%0], {%1, %2, %3, %4};"
                 :: "l"(addr), "f"(a), "f"(b), "f"(c), "f"(d) : "memory");
}

// ---------------- reset ------------------------------------------------------
__global__ void reset_k() {
    int i = threadIdx.x;                  // 512 threads
    if (i < NE) g_cnt[i] = 0;
    if (i == NE) g_cnt[NE] = TT;
    if (i < NSEG * 32) g_done[i] = 0;
    if (i == 500) g_ticket = 0;
}

// ---------------- fused aux: wcvt | zero | gate ------------------------------
__global__ void aux_k(const float* __restrict__ x,  const float* __restrict__ gw,
                      const float* __restrict__ sw1, const float* __restrict__ sw2,
                      const float* __restrict__ ew1, const float* __restrict__ ew2,
                      float* __restrict__ out) {
    int bid = blockIdx.x;
    if (bid < WCVT_BLKS) {
        int wsel = bid / 36864;
        int rem  = bid % 36864;
        int seg  = rem / 4096;
        int blk  = rem % 4096;
        size_t segoff = (size_t)seg * HH * DM;
        const float* src;
        __half* dst;
        if (wsel == 0) { src = (seg == NE) ? sw1 : (ew1 + segoff); dst = g_w1 + segoff; }
        else           { src = (seg == NE) ? sw2 : (ew2 + segoff); dst = g_w2 + segoff; }
        size_t i4 = (size_t)blk * 256 + threadIdx.x;
        float4 v = ((const float4*)src)[i4];
        __half2* p = (__half2*)(dst + i4 * 4);
        p[0] = __floats2half2_rn(v.x, v.y);
        p[1] = __floats2half2_rn(v.z, v.w);
        return;
    }
    bid -= WCVT_BLKS;
    if (bid < ZERO_BLKS) {
        size_t i = (size_t)bid * 256 + threadIdx.x;
        ((float4*)out)[i] = make_float4(0.f, 0.f, 0.f, 0.f);
        return;
    }
    bid -= ZERO_BLKS;
    {
        // ---- gating: one warp per token ----
        int gtid = bid * 256 + threadIdx.x;
        int t = gtid >> 5, lane = gtid & 31;
        const float* xr = x + (size_t)t * DM;
        float acc[NE];
#pragma unroll
        for (int e = 0; e < NE; e++) acc[e] = 0.f;
        for (int k = lane; k < DM; k += 32) {
            float xv = xr[k];
#pragma unroll
            for (int e = 0; e < NE; e++) acc[e] += xv * gw[e * DM + k];
        }
#pragma unroll
        for (int e = 0; e < NE; e++) {
#pragma unroll
            for (int o = 16; o > 0; o >>= 1) acc[e] += __shfl_xor_sync(0xffffffffu, acc[e], o);
        }
        if (lane == 0) {
            int i0 = 0; float v0 = acc[0];
#pragma unroll
            for (int e = 1; e < NE; e++) if (acc[e] > v0) { v0 = acc[e]; i0 = e; }
            int i1 = -1; float v1 = -1e30f;
#pragma unroll
            for (int e = 0; e < NE; e++) if (e != i0 && acc[e] > v1) { v1 = acc[e]; i1 = e; }
            float ex = expf(v1 - v0);
            float g0 = 1.f / (1.f + ex);
            float g1 = ex / (1.f + ex);
            int p0 = atomicAdd(&g_cnt[i0], 1);
            g_rowmap[i0 * CAP + p0] = t; g_sgate[i0 * CAP + p0] = g0;
            int p1 = atomicAdd(&g_cnt[i1], 1);
            g_rowmap[i1 * CAP + p1] = t; g_sgate[i1 * CAP + p1] = g1;
        }
    }
}

// ---------------- gather + convert activations per segment -------------------
__global__ void gather_k(const float* __restrict__ x) {
    int seg = blockIdx.y, slot = blockIdx.x;
    int cnt = g_cnt[seg];
    int pad = (cnt + 127) & ~127;
    if (slot >= pad) return;
    size_t drow = ((size_t)seg * CAP + slot) * DM;
    int i = threadIdx.x;
    float4 v = make_float4(0.f, 0.f, 0.f, 0.f);
    if (slot < cnt) {
        int tok = (seg == NE) ? slot : g_rowmap[seg * CAP + slot];
        v = ((const float4*)(x + (size_t)tok * DM))[i];
    }
    __half2* p = (__half2*)(g_x + drow + (size_t)i * 4);
    p[0] = __floats2half2_rn(v.x, v.y);
    p[1] = __floats2half2_rn(v.z, v.w);
}

// ---------------- GEMM core (verified R16 inner loop) ------------------------
// 128x128 CTA tile, 8 warps 64x32, 3-stage cp.async, occ 2
// PHASE 1 producer: h = silu(x @ W1^T) -> g_h, then signal g_done[seg][by]
// PHASE 2 consumer: waits g_done[seg][by]==32, out += gate*(h @ W2^T) via red.v4
template <int PHASE>
__device__ __forceinline__ void gemm_body(float* __restrict__ out,
                                          int bx, int by, int seg) {
    constexpr int KLEN = (PHASE == 1) ? DM : HH;
    constexpr int NDIM = (PHASE == 1) ? HH : DM;
    constexpr int NC   = KLEN / 64;

    const int cnt = g_cnt[seg];
    const int m0  = by * 128;
    if (m0 >= cnt) return;                       // consistent producer/consumer skip
    const int n0  = bx * 128;

    extern __shared__ char smem[];
    const uint32_t sb = s2u(smem);

    const int tid  = threadIdx.x;
    const int lane = tid & 31;
    const int warp = tid >> 5;
    const int wm   = (warp & 1) * 64;
    const int wn   = (warp >> 1) * 32;

    const __half* Asrc, * Bsrc;
    if (PHASE == 1) {
        Asrc = g_x  + ((size_t)seg * CAP  + m0) * KLEN;
        Bsrc = g_w1 + ((size_t)seg * NDIM + n0) * KLEN;
    } else {
        Asrc = g_h  + ((size_t)seg * CAP  + m0) * KLEN;
        Bsrc = g_w2 + ((size_t)seg * NDIM + n0) * KLEN;
    }

    if (PHASE == 2) {
        // wait for all 32 producer n-tiles of this (seg, by) slice
        if (tid == 0) {
            volatile int* dp = &g_done[seg * 32 + by];
            while (*dp < 32) __nanosleep(64);
            __threadfence();
        }
        __syncthreads();
    }

    auto issue = [&](int c) {
        uint32_t base = sb + (c % 3) * STAGE_B;
#pragma unroll
        for (int it = 0; it < 4; it++) {
            int o = tid + it * 256;
            int row = o >> 3, q = o & 7;
            cpasync16(base + row * 144 + q * 16,
                      Asrc + (size_t)row * KLEN + c * 64 + q * 8);
        }
#pragma unroll
        for (int it = 0; it < 4; it++) {
            int o = tid + it * 256;
            int row = o >> 3, q = o & 7;
            cpasync16(base + A_TILE_B + row * 144 + q * 16,
                      Bsrc + (size_t)row * KLEN + c * 64 + q * 8);
        }
        cp_commit();
    };

    float acc[4][4][4];
#pragma unroll
    for (int mi = 0; mi < 4; mi++)
#pragma unroll
        for (int ni = 0; ni < 4; ni++)
#pragma unroll
            for (int r = 0; r < 4; r++) acc[mi][ni][r] = 0.f;

    issue(0);
    issue(1);

    for (int c = 0; c < NC; c++) {
        if (c + 1 < NC) cp_wait<1>();
        else            cp_wait<0>();
        __syncthreads();
        if (c + 2 < NC) issue(c + 2);

        uint32_t Ab = sb + (c % 3) * STAGE_B;
        uint32_t Bb = Ab + A_TILE_B;

#pragma unroll
        for (int ks = 0; ks < 4; ks++) {
            const uint32_t acol = ks * 32 + (lane >> 4) * 16;
            const uint32_t bcol = ks * 32 + ((lane >> 3) & 1) * 16;
            uint32_t ah[4][4], bh[4][2];
#pragma unroll
            for (int mi = 0; mi < 4; mi++)
                ldsm4(ah[mi], Ab + (wm + mi * 16 + (lane & 15)) * 144 + acol);
#pragma unroll
            for (int ni = 0; ni < 4; ni++)
                ldsm2(bh[ni], Bb + (wn + ni * 8 + (lane & 7)) * 144 + bcol);
#pragma unroll
            for (int mi = 0; mi < 4; mi++)
#pragma unroll
                for (int ni = 0; ni < 4; ni++) mma16816(acc[mi][ni], ah[mi], bh[ni]);
        }
    }
    __syncthreads();

    // ---- epilogue: regs -> smem (f32, stride 132) -> gmem ----
    float* SF = (float*)smem;
    int*   RI = (int*)(smem + 128 * 132 * 4);
    float* GV = (float*)(smem + 128 * 132 * 4 + 512);

#pragma unroll
    for (int mi = 0; mi < 4; mi++)
#pragma unroll
        for (int ni = 0; ni < 4; ni++)
#pragma unroll
            for (int r = 0; r < 4; r++) {
                int row = wm + mi * 16 + (lane >> 2) + (r >> 1) * 8;
                int col = wn + ni * 8 + (lane & 3) * 2 + (r & 1);
                float v = acc[mi][ni][r];
                if (PHASE == 1) v = silu_f(v);
                SF[row * 132 + col] = v;
            }
    if (PHASE == 2 && tid < 128) {
        int m = m0 + tid;
        if (seg == NE)      { RI[tid] = m; GV[tid] = 1.f; }
        else if (m < cnt)   { RI[tid] = g_rowmap[seg * CAP + m]; GV[tid] = g_sgate[seg * CAP + m]; }
        else                { RI[tid] = 0; GV[tid] = 0.f; }
    }
    __syncthreads();

    if (PHASE == 1) {
        for (int i = tid; i < 128 * 32; i += 256) {
            int r = i >> 5, q = i & 31;
            float4 v = *(const float4*)(SF + r * 132 + q * 4);
            size_t drow = (size_t)seg * CAP + m0 + r;
            __half2* p = (__half2*)(g_h + drow * HH + n0 + q * 4);
            p[0] = __floats2half2_rn(v.x, v.y);
            p[1] = __floats2half2_rn(v.z, v.w);
        }
        // signal: this (seg, by, bx) slice of g_h is globally visible
        __threadfence();
        __syncthreads();
        if (tid == 0) atomicAdd(&g_done[seg * 32 + by], 1);
    } else {
        for (int i = tid; i < 128 * 32; i += 256) {
            int r = i >> 5, q = i & 31;
            float4 v = *(const float4*)(SF + r * 132 + q * 4);
            float gv = GV[r];
            float* op = out + (size_t)RI[r] * DM + n0 + q * 4;   // 16B-aligned
            red_add_v4(op, gv * v.x, gv * v.y, gv * v.z, gv * v.w);
        }
    }
}

// ---------------- merged gemm kernel: ticket-ordered producer/consumer -------
__global__ __launch_bounds__(256, 2) void gemm_fused_k(float* __restrict__ out) {
    __shared__ int s_tix;
    if (threadIdx.x == 0) s_tix = atomicAdd(&g_ticket, 1);
    __syncthreads();
    const int tix = s_tix;
    __syncthreads();
    if (tix < G1_TILES) {
        int bx  = tix & 31;          // HH/128 = 32
        int by  = (tix >> 5) & 31;   // CAP/128 = 32
        int seg = tix >> 10;
        gemm_body<1>(out, bx, by, seg);
    } else {
        int b   = tix - G1_TILES;
        int bx  = b & 7;             // DM/128 = 8
        int by  = (b >> 3) & 31;
        int seg = b >> 8;
        gemm_body<2>(out, bx, by, seg);
    }
}

// ---------------------------------------------------------------------------
extern "C" void kernel_launch(void* const* d_in, const int* in_sizes, int n_in,
                              void* d_out, int out_size) {
    const float* x   = (const float*)d_in[0];
    const float* sw1 = (const float*)d_in[1];
    const float* sw2 = (const float*)d_in[2];
    const float* ew1 = (const float*)d_in[3];
    const float* ew2 = (const float*)d_in[4];
    const float* gw  = (const float*)d_in[5];
    float* out = (float*)d_out;

    cudaFuncSetAttribute(gemm_fused_k, cudaFuncAttributeMaxDynamicSharedMemorySize, SMEM_SZ);

    reset_k<<<1, 512>>>();
    aux_k<<<WCVT_BLKS + ZERO_BLKS + GATE_BLKS, 256>>>(x, gw, sw1, sw2, ew1, ew2, out);
    gather_k<<<dim3(CAP, NSEG), 256>>>(x);
    gemm_fused_k<<<G1_TILES + G2_TILES, 256, SMEM_SZ>>>(out);
}